// round 9
// baseline (speedup 1.0000x reference)
#include <cuda_runtime.h>
#include <cuda_fp16.h>
#include <cstdint>
#include <math.h>

#define BWIN 4096
#define HNUM 8
#define LN100 4.6051701859880914f
#define LOG2E 1.4426950408889634f

// ---------------------------------------------------------------------------
// Scratch (__device__ globals: allocation-guard safe)
// ---------------------------------------------------------------------------
__device__ __align__(16) __half g_qkv16[(size_t)3 * BWIN * HNUM * 64 * 32];
__device__ __align__(16) __half g_w16[768 * 256];
__device__ __align__(16) __half g_pw16[256 * 256];
__device__ float g_bt[127 * 8];
__device__ float g_rpbm[(size_t)64 * HNUM * 64 * 64];

// ---------------------------------------------------------------------------
// Helpers
// ---------------------------------------------------------------------------
__device__ __forceinline__ unsigned s2u(const void* p) {
    return (unsigned)__cvta_generic_to_shared(p);
}
__device__ __forceinline__ void ldsm4(unsigned* r, unsigned a) {
    asm volatile("ldmatrix.sync.aligned.m8n8.x4.shared.b16 {%0,%1,%2,%3}, [%4];"
                 : "=r"(r[0]), "=r"(r[1]), "=r"(r[2]), "=r"(r[3]) : "r"(a));
}
__device__ __forceinline__ void ldsm4t(unsigned* r, unsigned a) {
    asm volatile("ldmatrix.sync.aligned.m8n8.x4.trans.shared.b16 {%0,%1,%2,%3}, [%4];"
                 : "=r"(r[0]), "=r"(r[1]), "=r"(r[2]), "=r"(r[3]) : "r"(a));
}
__device__ __forceinline__ void mma_f16(float* d, const unsigned* a, unsigned b0, unsigned b1) {
    asm volatile(
        "mma.sync.aligned.m16n8k16.row.col.f32.f16.f16.f32 "
        "{%0,%1,%2,%3},{%4,%5,%6,%7},{%8,%9},{%0,%1,%2,%3};"
        : "+f"(d[0]), "+f"(d[1]), "+f"(d[2]), "+f"(d[3])
        : "r"(a[0]), "r"(a[1]), "r"(a[2]), "r"(a[3]), "r"(b0), "r"(b1));
}
__device__ __forceinline__ unsigned pack2(float x, float y) {
    unsigned r;
    asm("cvt.rn.f16x2.f32 %0, %1, %2;" : "=r"(r) : "f"(y), "f"(x));  // lo=x, hi=y
    return r;
}
__device__ __forceinline__ void cpa16(unsigned d, const void* s) {
    asm volatile("cp.async.ca.shared.global [%0], [%1], 16;" :: "r"(d), "l"(s));
}

// ---------------------------------------------------------------------------
// One-time weight fp32 -> fp16 conversion
// ---------------------------------------------------------------------------
__global__ void wcvt_kernel(const float* __restrict__ qw, const float* __restrict__ pw) {
    int i = blockIdx.x * 256 + threadIdx.x;
    if (i < 768 * 256) g_w16[i] = __float2half_rn(qw[i]);
    else g_pw16[i - 768 * 256] = __float2half_rn(pw[i - 768 * 256]);
}

// ---------------------------------------------------------------------------
// CPB MLP table (127 x 8)
// ---------------------------------------------------------------------------
__global__ void cpb_table_kernel(const float* __restrict__ rel_table,
                                 const float* __restrict__ w1,
                                 const float* __restrict__ b1,
                                 const float* __restrict__ w2) {
    const int r = blockIdx.x;
    const float x = rel_table[r];
    __shared__ float red[256][8];
    float p[8];
#pragma unroll
    for (int h = 0; h < 8; h++) p[h] = 0.f;
    for (int j = threadIdx.x; j < 512; j += 256) {
        float hv = fmaxf(x * w1[j] + b1[j], 0.f);
#pragma unroll
        for (int h = 0; h < 8; h++) p[h] += hv * w2[h * 512 + j];
    }
#pragma unroll
    for (int h = 0; h < 8; h++) red[threadIdx.x][h] = p[h];
    __syncthreads();
    if (threadIdx.x < 8) {
        float s = 0.f;
        for (int i = 0; i < 256; i++) s += red[i][threadIdx.x];
        g_bt[r * 8 + threadIdx.x] = s;
    }
}

// ---------------------------------------------------------------------------
// rpbm[w][h][i][j] = 16*sigmoid(bt[rel_index[i][j]][h]) + mask[w][i][j]
// ---------------------------------------------------------------------------
__global__ void rpbm_kernel(const int* __restrict__ rel_index, const float* __restrict__ mask) {
    const int w = blockIdx.x;
    const int h = blockIdx.y;
    for (int idx = threadIdx.x; idx < 4096; idx += 256) {
        int r = __ldg(rel_index + idx);
        float v = 16.f / (1.f + expf(-g_bt[r * 8 + h]));
        g_rpbm[((size_t)w * HNUM + h) * 4096 + idx] = v + __ldg(mask + (size_t)w * 4096 + idx);
    }
}

// ---------------------------------------------------------------------------
// QKV GEMM (legacy mma.sync, R7 version — passing at 362.7us)
// ---------------------------------------------------------------------------
#define ASTR 264
#define BSTR 72
#define SMEM_GEMM ((128 * ASTR + 2 * 128 * BSTR) * 2)

__device__ __forceinline__ void load_chunk(__half* Bs, const __half* Wg,
                                           int buf, int ch, int tid) {
    const int nt = ch >> 2;
    const int kc = ch & 3;
    const __half* src = Wg + (size_t)(nt * 128) * 256 + kc * 64;
    __half* dst = Bs + buf * (128 * BSTR);
#pragma unroll
    for (int j = 0; j < 4; j++) {
        int idx = tid + j * 256;
        int row = idx >> 3;
        int c8 = (idx & 7) * 8;
        cpa16(s2u(dst + row * BSTR + c8), src + (size_t)row * 256 + c8);
    }
    asm volatile("cp.async.commit_group;");
}

__global__ __launch_bounds__(256) void gemm_qkv(const float* __restrict__ Ag,
                                                const float* __restrict__ bv_q,
                                                const float* __restrict__ bv_v,
                                                const float* __restrict__ logit_scale) {
    extern __shared__ __half smq[];
    __half* As = smq;
    __half* Bs = smq + 128 * ASTR;

    const int tid = threadIdx.x;
    const int warp = tid >> 5;
    const int lane = tid & 31;
    const int g = lane >> 2;
    const int t = lane & 3;
    const int wm = warp >> 2;
    const int wn = warp & 3;

    {
        const float4* xg = (const float4*)Ag + (size_t)blockIdx.x * 8192;
#pragma unroll
        for (int j = 0; j < 32; j++) {
            int idx = tid + j * 256;
            int row = idx >> 6;
            int c4 = idx & 63;
            float4 v = __ldg(xg + idx);
            uint2 pk;
            pk.x = pack2(v.x, v.y);
            pk.y = pack2(v.z, v.w);
            *(uint2*)&As[row * ASTR + c4 * 4] = pk;
        }
    }

    load_chunk(Bs, g_w16, 0, 0, tid);

    float acc[4][4][4];
#pragma unroll
    for (int mt = 0; mt < 4; mt++)
#pragma unroll
        for (int nf = 0; nf < 4; nf++)
#pragma unroll
            for (int j = 0; j < 4; j++) acc[mt][nf][j] = 0.f;

    const unsigned aBase = s2u(As) + ((wm * 64 + (lane & 15)) * ASTR + ((lane >> 4) & 1) * 8) * 2;
    const unsigned bBase = s2u(Bs) +
        (((lane & 7) + ((lane >> 4) & 1) * 8) * BSTR + ((lane >> 3) & 1) * 8) * 2;

    int buf = 0;
    for (int it = 0; it < 24; it++) {
        asm volatile("cp.async.wait_group 0;");
        __syncthreads();
        if (it + 1 < 24) load_chunk(Bs, g_w16, buf ^ 1, it + 1, tid);

        const int kc = it & 3;
#pragma unroll
        for (int ks = 0; ks < 4; ks++) {
            unsigned a[4][4];
#pragma unroll
            for (int mt = 0; mt < 4; mt++)
                ldsm4(a[mt], aBase + (mt * 16 * ASTR + kc * 64 + ks * 16) * 2);
#pragma unroll
            for (int nf2 = 0; nf2 < 2; nf2++) {
                unsigned b[4];
                ldsm4(b, bBase + (buf * 128 * BSTR + (wn * 32 + nf2 * 16) * BSTR + ks * 16) * 2);
#pragma unroll
                for (int mt = 0; mt < 4; mt++) {
                    mma_f16(acc[mt][nf2 * 2], a[mt], b[0], b[1]);
                    mma_f16(acc[mt][nf2 * 2 + 1], a[mt], b[2], b[3]);
                }
            }
        }

        if (kc == 3) {
            const int nt = it >> 2;
            const int colbase = nt * 128 + wn * 32;
            const int t3 = colbase >> 8;
            const int h = (colbase & 255) >> 5;
            float scale = 1.f;
            if (t3 == 0) scale = expf(fminf(__ldg(logit_scale + h), LN100));
            float2 bb[4];
#pragma unroll
            for (int nf = 0; nf < 4; nf++) {
                if (t3 == 0) {
                    bb[nf].x = __ldg(bv_q + h * 32 + nf * 8 + 2 * t);
                    bb[nf].y = __ldg(bv_q + h * 32 + nf * 8 + 2 * t + 1);
                } else if (t3 == 2) {
                    bb[nf].x = __ldg(bv_v + h * 32 + nf * 8 + 2 * t);
                    bb[nf].y = __ldg(bv_v + h * 32 + nf * 8 + 2 * t + 1);
                } else {
                    bb[nf].x = 0.f;
                    bb[nf].y = 0.f;
                }
            }
#pragma unroll
            for (int mt = 0; mt < 4; mt++) {
#pragma unroll
                for (int hf = 0; hf < 2; hf++) {
                    const int row = (int)(blockIdx.x * 128) + wm * 64 + mt * 16 + g + hf * 8;
                    const int bidx = row >> 6;
                    const int tok = row & 63;
                    float v[8];
#pragma unroll
                    for (int nf = 0; nf < 4; nf++) {
                        v[2 * nf] = acc[mt][nf][hf * 2] + bb[nf].x;
                        v[2 * nf + 1] = acc[mt][nf][hf * 2 + 1] + bb[nf].y;
                    }
                    if (t3 < 2) {
                        float ss = 0.f;
#pragma unroll
                        for (int i = 0; i < 8; i++) ss += v[i] * v[i];
                        ss += __shfl_xor_sync(0xffffffffu, ss, 1);
                        ss += __shfl_xor_sync(0xffffffffu, ss, 2);
                        float inv = 1.f / fmaxf(sqrtf(ss), 1e-12f);
                        if (t3 == 0) inv *= scale;
#pragma unroll
                        for (int i = 0; i < 8; i++) v[i] *= inv;
                    }
                    __half* dst = g_qkv16 +
                        (((size_t)t3 * BWIN + bidx) * HNUM + h) * 2048 + tok * 32;
#pragma unroll
                    for (int nf = 0; nf < 4; nf++)
                        *(unsigned*)&dst[nf * 8 + 2 * t] = pack2(v[2 * nf], v[2 * nf + 1]);
                }
            }
#pragma unroll
            for (int mt = 0; mt < 4; mt++)
#pragma unroll
                for (int nf = 0; nf < 4; nf++)
#pragma unroll
                    for (int j = 0; j < 4; j++) acc[mt][nf][j] = 0.f;
        }
        buf ^= 1;
    }
}

// ---------------------------------------------------------------------------
// Fused attention + proj. One CTA per window (4096 CTAs, 512 threads).
// Smem layout (halves):
//   [0      .. 20480)  Q: 8 heads x [64][40]
//   [20480  .. 40960)  K: same
//   [40960  .. 61440)  V: same
//   [61440  .. 78336)  Y: [64][264]
//   [78336  .. 112128) W: 2 x [64][264]  (proj weight tiles, double buffer)
// ---------------------------------------------------------------------------
#define YOFF 61440
#define WOFF 78336
#define WTILE 16896
#define FSM ((WOFF + 2 * WTILE) * 2)

__device__ __forceinline__ void load_ptile(unsigned dstb, int nt, int tid) {
#pragma unroll
    for (int j = 0; j < 4; j++) {
        int idx = tid + j * 512;
        int row = idx >> 5;
        int p = idx & 31;
        cpa16(dstb + (row * 264 + p * 8) * 2, g_pw16 + (size_t)(nt * 64 + row) * 256 + p * 8);
    }
    asm volatile("cp.async.commit_group;");
}

__global__ __launch_bounds__(512) void attnproj(const float* __restrict__ bias,
                                                float* __restrict__ outp) {
    extern __shared__ __half smf[];
    const unsigned sb = s2u(smf);
    const int b = blockIdx.x;
    const int w = b & 63;
    const int tid = threadIdx.x;
    const int warp = tid >> 5;
    const int lane = tid & 31;
    const int g = lane >> 2;
    const int t = lane & 3;

    // proj weight tile 0 in flight early (overlaps qkv load + attention)
    load_ptile(sb + WOFF * 2, 0, tid);

    // ---- phase 1: load q/k/v (all heads) into per-head [64][40] tiles ----
#pragma unroll
    for (int s = 0; s < 12; s++) {
        int idx = tid + s * 512;
        int tt = idx >> 11;
        int r = idx & 2047;
        int h = r >> 8;
        int row = (r >> 2) & 63;
        int c4 = r & 3;
        const uint4* src = (const uint4*)(g_qkv16 +
            (((size_t)tt * BWIN + b) * HNUM + h) * 2048 + row * 32 + c4 * 8);
        *(uint4*)&smf[tt * 20480 + h * 2560 + row * 40 + c4 * 8] = __ldg(src);
    }
    __syncthreads();

    // ---- phase 2: attention. warp -> head (warp>>1), rows (warp&1)*32.. ----
    const int h = warp >> 1;
    const int rbase = (warp & 1) * 32;
    const unsigned qB = sb + (h * 2560 + (rbase + (lane & 15)) * 40 + ((lane >> 4) & 1) * 8) * 2;
    const unsigned kB = sb + ((20480 + h * 2560) +
        ((lane & 7) + ((lane >> 4) & 1) * 8) * 40 + ((lane >> 3) & 1) * 8) * 2;
    const unsigned vB = sb + ((40960 + h * 2560) +
        ((lane & 7) + ((lane >> 3) & 1) * 8) * 40 + ((lane >> 4) & 1) * 8) * 2;

    float acc[2][8][4];
#pragma unroll
    for (int mt = 0; mt < 2; mt++)
#pragma unroll
        for (int nt = 0; nt < 8; nt++)
#pragma unroll
            for (int j = 0; j < 4; j++) acc[mt][nt][j] = 0.f;

#pragma unroll
    for (int kk = 0; kk < 2; kk++) {
        unsigned a[2][4];
        ldsm4(a[0], qB + (kk * 16) * 2);
        ldsm4(a[1], qB + (16 * 40 + kk * 16) * 2);
#pragma unroll
        for (int kn = 0; kn < 4; kn++) {
            unsigned bf[4];
            ldsm4(bf, kB + (kn * 16 * 40 + kk * 16) * 2);
#pragma unroll
            for (int mt = 0; mt < 2; mt++) {
                mma_f16(acc[mt][kn * 2], a[mt], bf[0], bf[1]);
                mma_f16(acc[mt][kn * 2 + 1], a[mt], bf[2], bf[3]);
            }
        }
    }

    const float* rp = g_rpbm + ((size_t)w * HNUM + h) * 4096;
    float inv0[2], inv1[2];
#pragma unroll
    for (int mt = 0; mt < 2; mt++) {
        const int rlo = rbase + mt * 16 + g;
        const int rhi = rlo + 8;
        float mx0 = -1e30f;
        float mx1 = -1e30f;
#pragma unroll
        for (int nt = 0; nt < 8; nt++) {
            const int col = nt * 8 + 2 * t;
            float2 v0 = *(const float2*)(rp + rlo * 64 + col);
            float2 v1 = *(const float2*)(rp + rhi * 64 + col);
            acc[mt][nt][0] += v0.x;
            acc[mt][nt][1] += v0.y;
            acc[mt][nt][2] += v1.x;
            acc[mt][nt][3] += v1.y;
            mx0 = fmaxf(mx0, fmaxf(acc[mt][nt][0], acc[mt][nt][1]));
            mx1 = fmaxf(mx1, fmaxf(acc[mt][nt][2], acc[mt][nt][3]));
        }
        mx0 = fmaxf(mx0, __shfl_xor_sync(0xffffffffu, mx0, 1));
        mx0 = fmaxf(mx0, __shfl_xor_sync(0xffffffffu, mx0, 2));
        mx1 = fmaxf(mx1, __shfl_xor_sync(0xffffffffu, mx1, 1));
        mx1 = fmaxf(mx1, __shfl_xor_sync(0xffffffffu, mx1, 2));

        float s0 = 0.f;
        float s1 = 0.f;
#pragma unroll
        for (int nt = 0; nt < 8; nt++) {
            acc[mt][nt][0] = exp2f((acc[mt][nt][0] - mx0) * LOG2E);
            acc[mt][nt][1] = exp2f((acc[mt][nt][1] - mx0) * LOG2E);
            acc[mt][nt][2] = exp2f((acc[mt][nt][2] - mx1) * LOG2E);
            acc[mt][nt][3] = exp2f((acc[mt][nt][3] - mx1) * LOG2E);
            s0 += acc[mt][nt][0] + acc[mt][nt][1];
            s1 += acc[mt][nt][2] + acc[mt][nt][3];
        }
        s0 += __shfl_xor_sync(0xffffffffu, s0, 1);
        s0 += __shfl_xor_sync(0xffffffffu, s0, 2);
        s1 += __shfl_xor_sync(0xffffffffu, s1, 1);
        s1 += __shfl_xor_sync(0xffffffffu, s1, 2);
        inv0[mt] = 1.f / s0;
        inv1[mt] = 1.f / s1;
    }

    float o[2][4][4];
#pragma unroll
    for (int mt = 0; mt < 2; mt++)
#pragma unroll
        for (int nf = 0; nf < 4; nf++)
#pragma unroll
            for (int j = 0; j < 4; j++) o[mt][nf][j] = 0.f;
#pragma unroll
    for (int kk = 0; kk < 4; kk++) {
        unsigned a[2][4];
#pragma unroll
        for (int mt = 0; mt < 2; mt++) {
            a[mt][0] = pack2(acc[mt][2 * kk][0], acc[mt][2 * kk][1]);
            a[mt][1] = pack2(acc[mt][2 * kk][2], acc[mt][2 * kk][3]);
            a[mt][2] = pack2(acc[mt][2 * kk + 1][0], acc[mt][2 * kk + 1][1]);
            a[mt][3] = pack2(acc[mt][2 * kk + 1][2], acc[mt][2 * kk + 1][3]);
        }
#pragma unroll
        for (int d = 0; d < 2; d++) {
            unsigned bf[4];
            ldsm4t(bf, vB + (kk * 16 * 40 + d * 16) * 2);
#pragma unroll
            for (int mt = 0; mt < 2; mt++) {
                mma_f16(o[mt][d * 2], a[mt], bf[0], bf[1]);
                mma_f16(o[mt][d * 2 + 1], a[mt], bf[2], bf[3]);
            }
        }
    }

    // y -> smem (fp16, stride 264)
#pragma unroll
    for (int mt = 0; mt < 2; mt++) {
        const int rlo = rbase + mt * 16 + g;
        const int rhi = rlo + 8;
#pragma unroll
        for (int nf = 0; nf < 4; nf++) {
            const int col = h * 32 + nf * 8 + 2 * t;
            *(unsigned*)&smf[YOFF + rlo * 264 + col] =
                pack2(o[mt][nf][0] * inv0[mt], o[mt][nf][1] * inv0[mt]);
            *(unsigned*)&smf[YOFF + rhi * 264 + col] =
                pack2(o[mt][nf][2] * inv1[mt], o[mt][nf][3] * inv1[mt]);
        }
    }

    // ---- phase 3: proj. warps 4(m) x 4(n); warp tile 16x16 per N-tile ----
    const int wm = warp >> 2;
    const int wn = warp & 3;
    const unsigned aB = sb + (YOFF + (wm * 16 + (lane & 15)) * 264 + ((lane >> 4) & 1) * 8) * 2;
    const unsigned bB = sb + (WOFF +
        (wn * 16 + (lane & 7) + ((lane >> 4) & 1) * 8) * 264 + ((lane >> 3) & 1) * 8) * 2;

    int buf = 0;
    for (int nt = 0; nt < 4; nt++) {
        asm volatile("cp.async.wait_group 0;");
        __syncthreads();
        if (nt + 1 < 4) load_ptile(sb + (WOFF + (buf ^ 1) * WTILE) * 2, nt + 1, tid);

        float pacc[2][4];
#pragma unroll
        for (int nf = 0; nf < 2; nf++)
#pragma unroll
            for (int j = 0; j < 4; j++) pacc[nf][j] = 0.f;

#pragma unroll
        for (int ks = 0; ks < 16; ks++) {
            unsigned a[4];
            unsigned bf[4];
            ldsm4(a, aB + (ks * 16) * 2);
            ldsm4(bf, bB + (buf * WTILE + ks * 16) * 2);
            mma_f16(pacc[0], a, bf[0], bf[1]);
            mma_f16(pacc[1], a, bf[2], bf[3]);
        }

        const int colb = nt * 64 + wn * 16;
#pragma unroll
        for (int nf = 0; nf < 2; nf++) {
            const int col = colb + nf * 8 + 2 * t;
            const float bx = __ldg(bias + col);
            const float by = __ldg(bias + col + 1);
#pragma unroll
            for (int hf = 0; hf < 2; hf++) {
                const int row = b * 64 + wm * 16 + g + hf * 8;
                float2 ov;
                ov.x = pacc[nf][hf * 2] + bx;
                ov.y = pacc[nf][hf * 2 + 1] + by;
                *(float2*)&outp[(size_t)row * 256 + col] = ov;
            }
        }
        buf ^= 1;
    }
}

// ---------------------------------------------------------------------------
// launch
// ---------------------------------------------------------------------------
extern "C" void kernel_launch(void* const* d_in, const int* in_sizes, int n_in,
                              void* d_out, int out_size) {
    const float* x           = (const float*)d_in[0];
    const float* mask        = (const float*)d_in[1];
    const float* qkv_w       = (const float*)d_in[2];
    const float* q_bias      = (const float*)d_in[3];
    const float* v_bias      = (const float*)d_in[4];
    const float* logit_scale = (const float*)d_in[5];
    const float* cpb_w1      = (const float*)d_in[6];
    const float* cpb_b1      = (const float*)d_in[7];
    const float* cpb_w2      = (const float*)d_in[8];
    const float* proj_w      = (const float*)d_in[9];
    const float* proj_b      = (const float*)d_in[10];
    const float* rel_table   = (const float*)d_in[11];
    const int*   rel_index   = (const int*)d_in[12];
    float* out = (float*)d_out;

    cudaFuncSetAttribute(gemm_qkv, cudaFuncAttributeMaxDynamicSharedMemorySize, SMEM_GEMM);
    cudaFuncSetAttribute(attnproj, cudaFuncAttributeMaxDynamicSharedMemorySize, FSM);

    wcvt_kernel<<<1024, 256>>>(qkv_w, proj_w);
    cpb_table_kernel<<<127, 256>>>(rel_table, cpb_w1, cpb_b1, cpb_w2);
    rpbm_kernel<<<dim3(64, 8), 256>>>(rel_index, mask);
    gemm_qkv<<<2048, 256, SMEM_GEMM>>>(x, q_bias, v_bias, logit_scale);
    attnproj<<<BWIN, 512, FSM>>>(proj_b, out);
}

// round 12
// speedup vs baseline: 1.1262x; 1.1262x over previous
#include <cuda_runtime.h>
#include <cuda_fp16.h>
#include <cstdint>
#include <math.h>

#define BWIN 4096
#define HNUM 8
#define LN100 4.6051701859880914f
#define LOG2E 1.4426950408889634f

// ---------------------------------------------------------------------------
// Scratch (__device__ globals: allocation-guard safe)
// ---------------------------------------------------------------------------
__device__ __align__(16) __half g_qkv16[(size_t)3 * BWIN * HNUM * 64 * 32];
__device__ __align__(16) __half g_y16[(size_t)BWIN * 64 * 256];
__device__ __align__(16) __half g_w16[768 * 256];
__device__ __align__(16) __half g_pw16[256 * 256];
__device__ float g_bt[127 * 8];
__device__ float g_rpbm[(size_t)64 * HNUM * 64 * 64];

// ---------------------------------------------------------------------------
// Helpers
// ---------------------------------------------------------------------------
__device__ __forceinline__ unsigned s2u(const void* p) {
    return (unsigned)__cvta_generic_to_shared(p);
}
__device__ __forceinline__ void ldsm4(unsigned* r, unsigned a) {
    asm volatile("ldmatrix.sync.aligned.m8n8.x4.shared.b16 {%0,%1,%2,%3}, [%4];"
                 : "=r"(r[0]), "=r"(r[1]), "=r"(r[2]), "=r"(r[3]) : "r"(a));
}
__device__ __forceinline__ void ldsm4t(unsigned* r, unsigned a) {
    asm volatile("ldmatrix.sync.aligned.m8n8.x4.trans.shared.b16 {%0,%1,%2,%3}, [%4];"
                 : "=r"(r[0]), "=r"(r[1]), "=r"(r[2]), "=r"(r[3]) : "r"(a));
}
__device__ __forceinline__ void mma_f16(float* d, const unsigned* a, unsigned b0, unsigned b1) {
    asm volatile(
        "mma.sync.aligned.m16n8k16.row.col.f32.f16.f16.f32 "
        "{%0,%1,%2,%3},{%4,%5,%6,%7},{%8,%9},{%0,%1,%2,%3};"
        : "+f"(d[0]), "+f"(d[1]), "+f"(d[2]), "+f"(d[3])
        : "r"(a[0]), "r"(a[1]), "r"(a[2]), "r"(a[3]), "r"(b0), "r"(b1));
}
__device__ __forceinline__ unsigned pack2(float x, float y) {
    unsigned r;
    asm("cvt.rn.f16x2.f32 %0, %1, %2;" : "=r"(r) : "f"(y), "f"(x));  // lo=x, hi=y
    return r;
}
__device__ __forceinline__ void cpa16(unsigned d, const void* s) {
    asm volatile("cp.async.ca.shared.global [%0], [%1], 16;" :: "r"(d), "l"(s));
}

// ---------------------------------------------------------------------------
// One-time weight fp32 -> fp16 conversion
// ---------------------------------------------------------------------------
__global__ void wcvt_kernel(const float* __restrict__ qw, const float* __restrict__ pw) {
    int i = blockIdx.x * 256 + threadIdx.x;
    if (i < 768 * 256) g_w16[i] = __float2half_rn(qw[i]);
    else g_pw16[i - 768 * 256] = __float2half_rn(pw[i - 768 * 256]);
}

// ---------------------------------------------------------------------------
// CPB MLP table (127 x 8)
// ---------------------------------------------------------------------------
__global__ void cpb_table_kernel(const float* __restrict__ rel_table,
                                 const float* __restrict__ w1,
                                 const float* __restrict__ b1,
                                 const float* __restrict__ w2) {
    const int r = blockIdx.x;
    const float x = rel_table[r];
    __shared__ float red[256][8];
    float p[8];
#pragma unroll
    for (int h = 0; h < 8; h++) p[h] = 0.f;
    for (int j = threadIdx.x; j < 512; j += 256) {
        float hv = fmaxf(x * w1[j] + b1[j], 0.f);
#pragma unroll
        for (int h = 0; h < 8; h++) p[h] += hv * w2[h * 512 + j];
    }
#pragma unroll
    for (int h = 0; h < 8; h++) red[threadIdx.x][h] = p[h];
    __syncthreads();
    if (threadIdx.x < 8) {
        float s = 0.f;
        for (int i = 0; i < 256; i++) s += red[i][threadIdx.x];
        g_bt[r * 8 + threadIdx.x] = s;
    }
}

// ---------------------------------------------------------------------------
// rpbm[w][h][i][j] = 16*sigmoid(bt[rel_index[i][j]][h]) + mask[w][i][j]
// ---------------------------------------------------------------------------
__global__ void rpbm_kernel(const int* __restrict__ rel_index, const float* __restrict__ mask) {
    const int w = blockIdx.x;
    const int h = blockIdx.y;
    for (int idx = threadIdx.x; idx < 4096; idx += 256) {
        int r = __ldg(rel_index + idx);
        float v = 16.f / (1.f + expf(-g_bt[r * 8 + h]));
        g_rpbm[((size_t)w * HNUM + h) * 4096 + idx] = v + __ldg(mask + (size_t)w * 4096 + idx);
    }
}

// ---------------------------------------------------------------------------
// QKV GEMM (legacy mma.sync, R7 version — verified, 362.7us)
// ---------------------------------------------------------------------------
#define ASTR 264
#define BSTR 72
#define SMEM_GEMM ((128 * ASTR + 2 * 128 * BSTR) * 2)

__device__ __forceinline__ void load_chunk(__half* Bs, const __half* Wg,
                                           int buf, int ch, int tid) {
    const int nt = ch >> 2;
    const int kc = ch & 3;
    const __half* src = Wg + (size_t)(nt * 128) * 256 + kc * 64;
    __half* dst = Bs + buf * (128 * BSTR);
#pragma unroll
    for (int j = 0; j < 4; j++) {
        int idx = tid + j * 256;
        int row = idx >> 3;
        int c8 = (idx & 7) * 8;
        cpa16(s2u(dst + row * BSTR + c8), src + (size_t)row * 256 + c8);
    }
    asm volatile("cp.async.commit_group;");
}

__global__ __launch_bounds__(256) void gemm_qkv(const float* __restrict__ Ag,
                                                const float* __restrict__ bv_q,
                                                const float* __restrict__ bv_v,
                                                const float* __restrict__ logit_scale) {
    extern __shared__ __half smq[];
    __half* As = smq;
    __half* Bs = smq + 128 * ASTR;

    const int tid = threadIdx.x;
    const int warp = tid >> 5;
    const int lane = tid & 31;
    const int g = lane >> 2;
    const int t = lane & 3;
    const int wm = warp >> 2;
    const int wn = warp & 3;

    {
        const float4* xg = (const float4*)Ag + (size_t)blockIdx.x * 8192;
#pragma unroll
        for (int j = 0; j < 32; j++) {
            int idx = tid + j * 256;
            int row = idx >> 6;
            int c4 = idx & 63;
            float4 v = __ldg(xg + idx);
            uint2 pk;
            pk.x = pack2(v.x, v.y);
            pk.y = pack2(v.z, v.w);
            *(uint2*)&As[row * ASTR + c4 * 4] = pk;
        }
    }

    load_chunk(Bs, g_w16, 0, 0, tid);

    float acc[4][4][4];
#pragma unroll
    for (int mt = 0; mt < 4; mt++)
#pragma unroll
        for (int nf = 0; nf < 4; nf++)
#pragma unroll
            for (int j = 0; j < 4; j++) acc[mt][nf][j] = 0.f;

    const unsigned aBase = s2u(As) + ((wm * 64 + (lane & 15)) * ASTR + ((lane >> 4) & 1) * 8) * 2;
    const unsigned bBase = s2u(Bs) +
        (((lane & 7) + ((lane >> 4) & 1) * 8) * BSTR + ((lane >> 3) & 1) * 8) * 2;

    int buf = 0;
    for (int it = 0; it < 24; it++) {
        asm volatile("cp.async.wait_group 0;");
        __syncthreads();
        if (it + 1 < 24) load_chunk(Bs, g_w16, buf ^ 1, it + 1, tid);

        const int kc = it & 3;
#pragma unroll
        for (int ks = 0; ks < 4; ks++) {
            unsigned a[4][4];
#pragma unroll
            for (int mt = 0; mt < 4; mt++)
                ldsm4(a[mt], aBase + (mt * 16 * ASTR + kc * 64 + ks * 16) * 2);
#pragma unroll
            for (int nf2 = 0; nf2 < 2; nf2++) {
                unsigned b[4];
                ldsm4(b, bBase + (buf * 128 * BSTR + (wn * 32 + nf2 * 16) * BSTR + ks * 16) * 2);
#pragma unroll
                for (int mt = 0; mt < 4; mt++) {
                    mma_f16(acc[mt][nf2 * 2], a[mt], b[0], b[1]);
                    mma_f16(acc[mt][nf2 * 2 + 1], a[mt], b[2], b[3]);
                }
            }
        }

        if (kc == 3) {
            const int nt = it >> 2;
            const int colbase = nt * 128 + wn * 32;
            const int t3 = colbase >> 8;
            const int h = (colbase & 255) >> 5;
            float scale = 1.f;
            if (t3 == 0) scale = expf(fminf(__ldg(logit_scale + h), LN100));
            float2 bb[4];
#pragma unroll
            for (int nf = 0; nf < 4; nf++) {
                if (t3 == 0) {
                    bb[nf].x = __ldg(bv_q + h * 32 + nf * 8 + 2 * t);
                    bb[nf].y = __ldg(bv_q + h * 32 + nf * 8 + 2 * t + 1);
                } else if (t3 == 2) {
                    bb[nf].x = __ldg(bv_v + h * 32 + nf * 8 + 2 * t);
                    bb[nf].y = __ldg(bv_v + h * 32 + nf * 8 + 2 * t + 1);
                } else {
                    bb[nf].x = 0.f;
                    bb[nf].y = 0.f;
                }
            }
#pragma unroll
            for (int mt = 0; mt < 4; mt++) {
#pragma unroll
                for (int hf = 0; hf < 2; hf++) {
                    const int row = (int)(blockIdx.x * 128) + wm * 64 + mt * 16 + g + hf * 8;
                    const int bidx = row >> 6;
                    const int tok = row & 63;
                    float v[8];
#pragma unroll
                    for (int nf = 0; nf < 4; nf++) {
                        v[2 * nf] = acc[mt][nf][hf * 2] + bb[nf].x;
                        v[2 * nf + 1] = acc[mt][nf][hf * 2 + 1] + bb[nf].y;
                    }
                    if (t3 < 2) {
                        float ss = 0.f;
#pragma unroll
                        for (int i = 0; i < 8; i++) ss += v[i] * v[i];
                        ss += __shfl_xor_sync(0xffffffffu, ss, 1);
                        ss += __shfl_xor_sync(0xffffffffu, ss, 2);
                        float inv = 1.f / fmaxf(sqrtf(ss), 1e-12f);
                        if (t3 == 0) inv *= scale;
#pragma unroll
                        for (int i = 0; i < 8; i++) v[i] *= inv;
                    }
                    __half* dst = g_qkv16 +
                        (((size_t)t3 * BWIN + bidx) * HNUM + h) * 2048 + tok * 32;
#pragma unroll
                    for (int nf = 0; nf < 4; nf++)
                        *(unsigned*)&dst[nf * 8 + 2 * t] = pack2(v[2 * nf], v[2 * nf + 1]);
                }
            }
#pragma unroll
            for (int mt = 0; mt < 4; mt++)
#pragma unroll
                for (int nf = 0; nf < 4; nf++)
#pragma unroll
                    for (int j = 0; j < 4; j++) acc[mt][nf][j] = 0.f;
        }
        buf ^= 1;
    }
}

// ---------------------------------------------------------------------------
// Attention: one CTA per (window, 4-head group). 256 threads = 8 warps;
// warp = (head-in-group = warp>>1, 32-row half = (warp&1)*32).
// smem 61.44KB dynamic; __launch_bounds__(256,2) -> 128 regs, 2 CTAs/SM.
// Per-warp math identical to the verified attn16/R9 code.
// ---------------------------------------------------------------------------
#define ATSM 61440

__global__ __launch_bounds__(256, 2) void attn4h() {
    extern __shared__ __half smf[];
    const unsigned sb = s2u(smf);
    const int b = blockIdx.x >> 1;
    const int g2 = blockIdx.x & 1;
    const int w = b & 63;
    const int tid = threadIdx.x;
    const int warp = tid >> 5;
    const int lane = tid & 31;
    const int g = lane >> 2;
    const int t = lane & 3;

    // ---- phase 1: load q/k/v for 4 heads into per-head [64][40] tiles ----
#pragma unroll
    for (int s = 0; s < 12; s++) {
        int idx = tid + s * 256;
        int tt = idx >> 10;          // tensor (q/k/v): 1024 uint4 each
        int r = idx & 1023;
        int h4 = r >> 8;             // head in group
        int row = (r >> 2) & 63;
        int c4 = r & 3;
        const uint4* src = (const uint4*)(g_qkv16 +
            (((size_t)tt * BWIN + b) * HNUM + g2 * 4 + h4) * 2048 + row * 32 + c4 * 8);
        *(uint4*)&smf[tt * 10240 + h4 * 2560 + row * 40 + c4 * 8] = __ldg(src);
    }
    __syncthreads();

    // ---- phase 2: attention ----
    const int h4 = warp >> 1;
    const int h = g2 * 4 + h4;
    const int rbase = (warp & 1) * 32;
    const unsigned qB = sb + (h4 * 2560 + (rbase + (lane & 15)) * 40 + ((lane >> 4) & 1) * 8) * 2;
    const unsigned kB = sb + ((10240 + h4 * 2560) +
        ((lane & 7) + ((lane >> 4) & 1) * 8) * 40 + ((lane >> 3) & 1) * 8) * 2;
    const unsigned vB = sb + ((20480 + h4 * 2560) +
        ((lane & 7) + ((lane >> 3) & 1) * 8) * 40 + ((lane >> 4) & 1) * 8) * 2;

    float acc[2][8][4];
#pragma unroll
    for (int mt = 0; mt < 2; mt++)
#pragma unroll
        for (int nt = 0; nt < 8; nt++)
#pragma unroll
            for (int j = 0; j < 4; j++) acc[mt][nt][j] = 0.f;

#pragma unroll
    for (int kk = 0; kk < 2; kk++) {
        unsigned a[2][4];
        ldsm4(a[0], qB + (kk * 16) * 2);
        ldsm4(a[1], qB + (16 * 40 + kk * 16) * 2);
#pragma unroll
        for (int kn = 0; kn < 4; kn++) {
            unsigned bf[4];
            ldsm4(bf, kB + (kn * 16 * 40 + kk * 16) * 2);
#pragma unroll
            for (int mt = 0; mt < 2; mt++) {
                mma_f16(acc[mt][kn * 2], a[mt], bf[0], bf[1]);
                mma_f16(acc[mt][kn * 2 + 1], a[mt], bf[2], bf[3]);
            }
        }
    }

    const float* rp = g_rpbm + ((size_t)w * HNUM + h) * 4096;
    float inv0[2], inv1[2];
#pragma unroll
    for (int mt = 0; mt < 2; mt++) {
        const int rlo = rbase + mt * 16 + g;
        const int rhi = rlo + 8;
        float mx0 = -1e30f;
        float mx1 = -1e30f;
#pragma unroll
        for (int nt = 0; nt < 8; nt++) {
            const int col = nt * 8 + 2 * t;
            float2 v0 = *(const float2*)(rp + rlo * 64 + col);
            float2 v1 = *(const float2*)(rp + rhi * 64 + col);
            acc[mt][nt][0] += v0.x;
            acc[mt][nt][1] += v0.y;
            acc[mt][nt][2] += v1.x;
            acc[mt][nt][3] += v1.y;
            mx0 = fmaxf(mx0, fmaxf(acc[mt][nt][0], acc[mt][nt][1]));
            mx1 = fmaxf(mx1, fmaxf(acc[mt][nt][2], acc[mt][nt][3]));
        }
        mx0 = fmaxf(mx0, __shfl_xor_sync(0xffffffffu, mx0, 1));
        mx0 = fmaxf(mx0, __shfl_xor_sync(0xffffffffu, mx0, 2));
        mx1 = fmaxf(mx1, __shfl_xor_sync(0xffffffffu, mx1, 1));
        mx1 = fmaxf(mx1, __shfl_xor_sync(0xffffffffu, mx1, 2));

        float s0 = 0.f;
        float s1 = 0.f;
#pragma unroll
        for (int nt = 0; nt < 8; nt++) {
            acc[mt][nt][0] = exp2f((acc[mt][nt][0] - mx0) * LOG2E);
            acc[mt][nt][1] = exp2f((acc[mt][nt][1] - mx0) * LOG2E);
            acc[mt][nt][2] = exp2f((acc[mt][nt][2] - mx1) * LOG2E);
            acc[mt][nt][3] = exp2f((acc[mt][nt][3] - mx1) * LOG2E);
            s0 += acc[mt][nt][0] + acc[mt][nt][1];
            s1 += acc[mt][nt][2] + acc[mt][nt][3];
        }
        s0 += __shfl_xor_sync(0xffffffffu, s0, 1);
        s0 += __shfl_xor_sync(0xffffffffu, s0, 2);
        s1 += __shfl_xor_sync(0xffffffffu, s1, 1);
        s1 += __shfl_xor_sync(0xffffffffu, s1, 2);
        inv0[mt] = 1.f / s0;
        inv1[mt] = 1.f / s1;
    }

    float o[2][4][4];
#pragma unroll
    for (int mt = 0; mt < 2; mt++)
#pragma unroll
        for (int nf = 0; nf < 4; nf++)
#pragma unroll
            for (int j = 0; j < 4; j++) o[mt][nf][j] = 0.f;
#pragma unroll
    for (int kk = 0; kk < 4; kk++) {
        unsigned a[2][4];
#pragma unroll
        for (int mt = 0; mt < 2; mt++) {
            a[mt][0] = pack2(acc[mt][2 * kk][0], acc[mt][2 * kk][1]);
            a[mt][1] = pack2(acc[mt][2 * kk][2], acc[mt][2 * kk][3]);
            a[mt][2] = pack2(acc[mt][2 * kk + 1][0], acc[mt][2 * kk + 1][1]);
            a[mt][3] = pack2(acc[mt][2 * kk + 1][2], acc[mt][2 * kk + 1][3]);
        }
#pragma unroll
        for (int d = 0; d < 2; d++) {
            unsigned bf[4];
            ldsm4t(bf, vB + (kk * 16 * 40 + d * 16) * 2);
#pragma unroll
            for (int mt = 0; mt < 2; mt++) {
                mma_f16(o[mt][d * 2], a[mt], bf[0], bf[1]);
                mma_f16(o[mt][d * 2 + 1], a[mt], bf[2], bf[3]);
            }
        }
    }

    __half* yb = g_y16 + (size_t)b * 64 * 256 + h * 32;
#pragma unroll
    for (int mt = 0; mt < 2; mt++) {
        const int rlo = rbase + mt * 16 + g;
        const int rhi = rlo + 8;
#pragma unroll
        for (int nf = 0; nf < 4; nf++) {
            const int col = nf * 8 + 2 * t;
            *(unsigned*)&yb[(size_t)rlo * 256 + col] =
                pack2(o[mt][nf][0] * inv0[mt], o[mt][nf][1] * inv0[mt]);
            *(unsigned*)&yb[(size_t)rhi * 256 + col] =
                pack2(o[mt][nf][2] * inv1[mt], o[mt][nf][3] * inv1[mt]);
        }
    }
}

// ---------------------------------------------------------------------------
// Proj GEMM (legacy mma.sync, R7 version — verified)
// ---------------------------------------------------------------------------
__global__ __launch_bounds__(256) void gemm_proj(const float* __restrict__ bias,
                                                 float* __restrict__ outp) {
    extern __shared__ __half smp[];
    __half* As = smp;
    __half* Bs = smp + 128 * ASTR;

    const int tid = threadIdx.x;
    const int warp = tid >> 5;
    const int lane = tid & 31;
    const int g = lane >> 2;
    const int t = lane & 3;
    const int wm = warp >> 2;
    const int wn = warp & 3;

    {
        const uint4* yg = (const uint4*)(g_y16 + (size_t)blockIdx.x * 128 * 256);
#pragma unroll
        for (int j = 0; j < 16; j++) {
            int idx = tid + j * 256;
            int row = idx >> 5;
            int c8 = (idx & 31) * 8;
            *(uint4*)&As[row * ASTR + c8] = __ldg(yg + idx);
        }
    }

    load_chunk(Bs, g_pw16, 0, 0, tid);

    float acc[4][4][4];
#pragma unroll
    for (int mt = 0; mt < 4; mt++)
#pragma unroll
        for (int nf = 0; nf < 4; nf++)
#pragma unroll
            for (int j = 0; j < 4; j++) acc[mt][nf][j] = 0.f;

    const unsigned aBase = s2u(As) + ((wm * 64 + (lane & 15)) * ASTR + ((lane >> 4) & 1) * 8) * 2;
    const unsigned bBase = s2u(Bs) +
        (((lane & 7) + ((lane >> 4) & 1) * 8) * BSTR + ((lane >> 3) & 1) * 8) * 2;

    int buf = 0;
    for (int it = 0; it < 8; it++) {
        asm volatile("cp.async.wait_group 0;");
        __syncthreads();
        if (it + 1 < 8) load_chunk(Bs, g_pw16, buf ^ 1, it + 1, tid);

        const int kc = it & 3;
#pragma unroll
        for (int ks = 0; ks < 4; ks++) {
            unsigned a[4][4];
#pragma unroll
            for (int mt = 0; mt < 4; mt++)
                ldsm4(a[mt], aBase + (mt * 16 * ASTR + kc * 64 + ks * 16) * 2);
#pragma unroll
            for (int nf2 = 0; nf2 < 2; nf2++) {
                unsigned b[4];
                ldsm4(b, bBase + (buf * 128 * BSTR + (wn * 32 + nf2 * 16) * BSTR + ks * 16) * 2);
#pragma unroll
                for (int mt = 0; mt < 4; mt++) {
                    mma_f16(acc[mt][nf2 * 2], a[mt], b[0], b[1]);
                    mma_f16(acc[mt][nf2 * 2 + 1], a[mt], b[2], b[3]);
                }
            }
        }

        if (kc == 3) {
            const int nt = it >> 2;
            const int colb = nt * 128 + wn * 32;
#pragma unroll
            for (int mt = 0; mt < 4; mt++) {
#pragma unroll
                for (int hf = 0; hf < 2; hf++) {
                    const int row = (int)(blockIdx.x * 128) + wm * 64 + mt * 16 + g + hf * 8;
#pragma unroll
                    for (int nf = 0; nf < 4; nf++) {
                        const int col = colb + nf * 8 + 2 * t;
                        float2 o;
                        o.x = acc[mt][nf][hf * 2] + __ldg(bias + col);
                        o.y = acc[mt][nf][hf * 2 + 1] + __ldg(bias + col + 1);
                        *(float2*)&outp[(size_t)row * 256 + col] = o;
                    }
                }
            }
#pragma unroll
            for (int mt = 0; mt < 4; mt++)
#pragma unroll
                for (int nf = 0; nf < 4; nf++)
#pragma unroll
                    for (int j = 0; j < 4; j++) acc[mt][nf][j] = 0.f;
        }
        buf ^= 1;
    }
}

// ---------------------------------------------------------------------------
// launch
// ---------------------------------------------------------------------------
extern "C" void kernel_launch(void* const* d_in, const int* in_sizes, int n_in,
                              void* d_out, int out_size) {
    const float* x           = (const float*)d_in[0];
    const float* mask        = (const float*)d_in[1];
    const float* qkv_w       = (const float*)d_in[2];
    const float* q_bias      = (const float*)d_in[3];
    const float* v_bias      = (const float*)d_in[4];
    const float* logit_scale = (const float*)d_in[5];
    const float* cpb_w1      = (const float*)d_in[6];
    const float* cpb_b1      = (const float*)d_in[7];
    const float* cpb_w2      = (const float*)d_in[8];
    const float* proj_w      = (const float*)d_in[9];
    const float* proj_b      = (const float*)d_in[10];
    const float* rel_table   = (const float*)d_in[11];
    const int*   rel_index   = (const int*)d_in[12];
    float* out = (float*)d_out;

    cudaFuncSetAttribute(gemm_qkv, cudaFuncAttributeMaxDynamicSharedMemorySize, SMEM_GEMM);
    cudaFuncSetAttribute(gemm_proj, cudaFuncAttributeMaxDynamicSharedMemorySize, SMEM_GEMM);
    cudaFuncSetAttribute(attn4h, cudaFuncAttributeMaxDynamicSharedMemorySize, ATSM);

    wcvt_kernel<<<1024, 256>>>(qkv_w, proj_w);
    cpb_table_kernel<<<127, 256>>>(rel_table, cpb_w1, cpb_b1, cpb_w2);
    rpbm_kernel<<<dim3(64, 8), 256>>>(rel_index, mask);
    gemm_qkv<<<2048, 256, SMEM_GEMM>>>(x, q_bias, v_bias, logit_scale);
    attn4h<<<BWIN * 2, 256, ATSM>>>();
    gemm_proj<<<2048, 256, SMEM_GEMM>>>(proj_b, out);
}

// round 13
// speedup vs baseline: 1.1804x; 1.0481x over previous
#include <cuda_runtime.h>
#include <cuda_fp16.h>
#include <cstdint>
#include <math.h>

#define BWIN 4096
#define HNUM 8
#define LN100 4.6051701859880914f
#define LOG2E 1.4426950408889634f

// ---------------------------------------------------------------------------
// Scratch (__device__ globals: allocation-guard safe)
// ---------------------------------------------------------------------------
__device__ __align__(16) __half g_qkv16[(size_t)3 * BWIN * HNUM * 64 * 32];
__device__ __align__(16) __half g_y16[(size_t)BWIN * 64 * 256];
__device__ __align__(16) __half g_w16[768 * 256];
__device__ __align__(16) __half g_pw16[256 * 256];
__device__ float g_bt[127 * 8];
__device__ float g_rpbm[(size_t)64 * HNUM * 64 * 64];

// ---------------------------------------------------------------------------
// Helpers
// ---------------------------------------------------------------------------
__device__ __forceinline__ unsigned s2u(const void* p) {
    return (unsigned)__cvta_generic_to_shared(p);
}
__device__ __forceinline__ void ldsm4(unsigned* r, unsigned a) {
    asm volatile("ldmatrix.sync.aligned.m8n8.x4.shared.b16 {%0,%1,%2,%3}, [%4];"
                 : "=r"(r[0]), "=r"(r[1]), "=r"(r[2]), "=r"(r[3]) : "r"(a));
}
__device__ __forceinline__ void ldsm4t(unsigned* r, unsigned a) {
    asm volatile("ldmatrix.sync.aligned.m8n8.x4.trans.shared.b16 {%0,%1,%2,%3}, [%4];"
                 : "=r"(r[0]), "=r"(r[1]), "=r"(r[2]), "=r"(r[3]) : "r"(a));
}
__device__ __forceinline__ void mma_f16(float* d, const unsigned* a, unsigned b0, unsigned b1) {
    asm volatile(
        "mma.sync.aligned.m16n8k16.row.col.f32.f16.f16.f32 "
        "{%0,%1,%2,%3},{%4,%5,%6,%7},{%8,%9},{%0,%1,%2,%3};"
        : "+f"(d[0]), "+f"(d[1]), "+f"(d[2]), "+f"(d[3])
        : "r"(a[0]), "r"(a[1]), "r"(a[2]), "r"(a[3]), "r"(b0), "r"(b1));
}
__device__ __forceinline__ unsigned pack2(float x, float y) {
    unsigned r;
    asm("cvt.rn.f16x2.f32 %0, %1, %2;" : "=r"(r) : "f"(y), "f"(x));  // lo=x, hi=y
    return r;
}
__device__ __forceinline__ void cpa16(unsigned d, const void* s) {
    asm volatile("cp.async.ca.shared.global [%0], [%1], 16;" :: "r"(d), "l"(s));
}

// select a[i] for runtime i in 0..3 without local memory
__device__ __forceinline__ unsigned sel4(const unsigned* a, int i) {
    unsigned lo = (i & 1) ? a[1] : a[0];
    unsigned hi = (i & 1) ? a[3] : a[2];
    return (i & 2) ? hi : lo;
}
// 4x4 u32 transpose within a quad (lanes g*4+t). In: pk[nf] = cols {8nf+2t,+1}.
// Out: pk[j] = cols {8t+2j,+1} -> thread holds contiguous cols 8t..8t+7.
__device__ __forceinline__ void trans4(unsigned* pk, int t) {
    unsigned rv[4];
    rv[0] = sel4(pk, t);
    rv[1] = __shfl_xor_sync(0xffffffffu, sel4(pk, t ^ 1), 1);
    rv[2] = __shfl_xor_sync(0xffffffffu, sel4(pk, t ^ 2), 2);
    rv[3] = __shfl_xor_sync(0xffffffffu, sel4(pk, t ^ 3), 3);
    unsigned o0 = sel4(rv, t);
    unsigned o1 = sel4(rv, t ^ 1);
    unsigned o2 = sel4(rv, t ^ 2);
    unsigned o3 = sel4(rv, t ^ 3);
    pk[0] = o0; pk[1] = o1; pk[2] = o2; pk[3] = o3;
}

// ---------------------------------------------------------------------------
// One-time weight fp32 -> fp16 conversion
// ---------------------------------------------------------------------------
__global__ void wcvt_kernel(const float* __restrict__ qw, const float* __restrict__ pw) {
    int i = blockIdx.x * 256 + threadIdx.x;
    if (i < 768 * 256) g_w16[i] = __float2half_rn(qw[i]);
    else g_pw16[i - 768 * 256] = __float2half_rn(pw[i - 768 * 256]);
}

// ---------------------------------------------------------------------------
// CPB MLP table (127 x 8)
// ---------------------------------------------------------------------------
__global__ void cpb_table_kernel(const float* __restrict__ rel_table,
                                 const float* __restrict__ w1,
                                 const float* __restrict__ b1,
                                 const float* __restrict__ w2) {
    const int r = blockIdx.x;
    const float x = rel_table[r];
    __shared__ float red[256][8];
    float p[8];
#pragma unroll
    for (int h = 0; h < 8; h++) p[h] = 0.f;
    for (int j = threadIdx.x; j < 512; j += 256) {
        float hv = fmaxf(x * w1[j] + b1[j], 0.f);
#pragma unroll
        for (int h = 0; h < 8; h++) p[h] += hv * w2[h * 512 + j];
    }
#pragma unroll
    for (int h = 0; h < 8; h++) red[threadIdx.x][h] = p[h];
    __syncthreads();
    if (threadIdx.x < 8) {
        float s = 0.f;
        for (int i = 0; i < 256; i++) s += red[i][threadIdx.x];
        g_bt[r * 8 + threadIdx.x] = s;
    }
}

// ---------------------------------------------------------------------------
// rpbm[w][h][i][j] = 16*sigmoid(bt[rel_index[i][j]][h]) + mask[w][i][j]
// ---------------------------------------------------------------------------
__global__ void rpbm_kernel(const int* __restrict__ rel_index, const float* __restrict__ mask) {
    const int w = blockIdx.x;
    const int h = blockIdx.y;
    for (int idx = threadIdx.x; idx < 4096; idx += 256) {
        int r = __ldg(rel_index + idx);
        float v = 16.f / (1.f + expf(-g_bt[r * 8 + h]));
        g_rpbm[((size_t)w * HNUM + h) * 4096 + idx] = v + __ldg(mask + (size_t)w * 4096 + idx);
    }
}

// ---------------------------------------------------------------------------
// QKV GEMM (legacy mma.sync, R7 structure; epilogue stores via quad-transpose)
// ---------------------------------------------------------------------------
#define ASTR 264
#define BSTR 72
#define SMEM_GEMM ((128 * ASTR + 2 * 128 * BSTR) * 2)

__device__ __forceinline__ void load_chunk(__half* Bs, const __half* Wg,
                                           int buf, int ch, int tid) {
    const int nt = ch >> 2;
    const int kc = ch & 3;
    const __half* src = Wg + (size_t)(nt * 128) * 256 + kc * 64;
    __half* dst = Bs + buf * (128 * BSTR);
#pragma unroll
    for (int j = 0; j < 4; j++) {
        int idx = tid + j * 256;
        int row = idx >> 3;
        int c8 = (idx & 7) * 8;
        cpa16(s2u(dst + row * BSTR + c8), src + (size_t)row * 256 + c8);
    }
    asm volatile("cp.async.commit_group;");
}

__global__ __launch_bounds__(256) void gemm_qkv(const float* __restrict__ Ag,
                                                const float* __restrict__ bv_q,
                                                const float* __restrict__ bv_v,
                                                const float* __restrict__ logit_scale) {
    extern __shared__ __half smq[];
    __half* As = smq;
    __half* Bs = smq + 128 * ASTR;

    const int tid = threadIdx.x;
    const int warp = tid >> 5;
    const int lane = tid & 31;
    const int g = lane >> 2;
    const int t = lane & 3;
    const int wm = warp >> 2;
    const int wn = warp & 3;

    {
        const float4* xg = (const float4*)Ag + (size_t)blockIdx.x * 8192;
#pragma unroll
        for (int j = 0; j < 32; j++) {
            int idx = tid + j * 256;
            int row = idx >> 6;
            int c4 = idx & 63;
            float4 v = __ldg(xg + idx);
            uint2 pk;
            pk.x = pack2(v.x, v.y);
            pk.y = pack2(v.z, v.w);
            *(uint2*)&As[row * ASTR + c4 * 4] = pk;
        }
    }

    load_chunk(Bs, g_w16, 0, 0, tid);

    float acc[4][4][4];
#pragma unroll
    for (int mt = 0; mt < 4; mt++)
#pragma unroll
        for (int nf = 0; nf < 4; nf++)
#pragma unroll
            for (int j = 0; j < 4; j++) acc[mt][nf][j] = 0.f;

    const unsigned aBase = s2u(As) + ((wm * 64 + (lane & 15)) * ASTR + ((lane >> 4) & 1) * 8) * 2;
    const unsigned bBase = s2u(Bs) +
        (((lane & 7) + ((lane >> 4) & 1) * 8) * BSTR + ((lane >> 3) & 1) * 8) * 2;

    int buf = 0;
    for (int it = 0; it < 24; it++) {
        asm volatile("cp.async.wait_group 0;");
        __syncthreads();
        if (it + 1 < 24) load_chunk(Bs, g_w16, buf ^ 1, it + 1, tid);

        const int kc = it & 3;
#pragma unroll
        for (int ks = 0; ks < 4; ks++) {
            unsigned a[4][4];
#pragma unroll
            for (int mt = 0; mt < 4; mt++)
                ldsm4(a[mt], aBase + (mt * 16 * ASTR + kc * 64 + ks * 16) * 2);
#pragma unroll
            for (int nf2 = 0; nf2 < 2; nf2++) {
                unsigned b[4];
                ldsm4(b, bBase + (buf * 128 * BSTR + (wn * 32 + nf2 * 16) * BSTR + ks * 16) * 2);
#pragma unroll
                for (int mt = 0; mt < 4; mt++) {
                    mma_f16(acc[mt][nf2 * 2], a[mt], b[0], b[1]);
                    mma_f16(acc[mt][nf2 * 2 + 1], a[mt], b[2], b[3]);
                }
            }
        }

        if (kc == 3) {
            const int nt = it >> 2;
            const int colbase = nt * 128 + wn * 32;
            const int t3 = colbase >> 8;
            const int h = (colbase & 255) >> 5;
            float scale = 1.f;
            if (t3 == 0) scale = expf(fminf(__ldg(logit_scale + h), LN100));
            float2 bb[4];
#pragma unroll
            for (int nf = 0; nf < 4; nf++) {
                if (t3 == 0) {
                    bb[nf].x = __ldg(bv_q + h * 32 + nf * 8 + 2 * t);
                    bb[nf].y = __ldg(bv_q + h * 32 + nf * 8 + 2 * t + 1);
                } else if (t3 == 2) {
                    bb[nf].x = __ldg(bv_v + h * 32 + nf * 8 + 2 * t);
                    bb[nf].y = __ldg(bv_v + h * 32 + nf * 8 + 2 * t + 1);
                } else {
                    bb[nf].x = 0.f;
                    bb[nf].y = 0.f;
                }
            }
#pragma unroll
            for (int mt = 0; mt < 4; mt++) {
#pragma unroll
                for (int hf = 0; hf < 2; hf++) {
                    const int row = (int)(blockIdx.x * 128) + wm * 64 + mt * 16 + g + hf * 8;
                    const int bidx = row >> 6;
                    const int tok = row & 63;
                    float v[8];
#pragma unroll
                    for (int nf = 0; nf < 4; nf++) {
                        v[2 * nf] = acc[mt][nf][hf * 2] + bb[nf].x;
                        v[2 * nf + 1] = acc[mt][nf][hf * 2 + 1] + bb[nf].y;
                    }
                    if (t3 < 2) {
                        float ss = 0.f;
#pragma unroll
                        for (int i = 0; i < 8; i++) ss += v[i] * v[i];
                        ss += __shfl_xor_sync(0xffffffffu, ss, 1);
                        ss += __shfl_xor_sync(0xffffffffu, ss, 2);
                        float inv = 1.f / fmaxf(sqrtf(ss), 1e-12f);
                        if (t3 == 0) inv *= scale;
#pragma unroll
                        for (int i = 0; i < 8; i++) v[i] *= inv;
                    }
                    // pack + quad transpose -> one coalesced 16B store per thread
                    unsigned pk[4];
#pragma unroll
                    for (int nf = 0; nf < 4; nf++)
                        pk[nf] = pack2(v[2 * nf], v[2 * nf + 1]);
                    trans4(pk, t);
                    __half* dst = g_qkv16 +
                        (((size_t)t3 * BWIN + bidx) * HNUM + h) * 2048 + tok * 32;
                    *(uint4*)&dst[t * 8] = make_uint4(pk[0], pk[1], pk[2], pk[3]);
                }
            }
#pragma unroll
            for (int mt = 0; mt < 4; mt++)
#pragma unroll
                for (int nf = 0; nf < 4; nf++)
#pragma unroll
                    for (int j = 0; j < 4; j++) acc[mt][nf][j] = 0.f;
        }
        buf ^= 1;
    }
}

// ---------------------------------------------------------------------------
// Attention: one CTA per (b,h), 4 warps x 16 q-rows (R7 version);
// y store via quad transpose (coalesced 16B stores).
// ---------------------------------------------------------------------------
__global__ __launch_bounds__(128) void attn16() {
    __shared__ __half Qs[64 * 40];
    __shared__ __half Ks[64 * 40];
    __shared__ __half Vs[64 * 40];
    const int bh = blockIdx.x;
    const int b = bh >> 3;
    const int h = bh & 7;
    const int w = b & 63;
    const __half* qg = g_qkv16 + ((size_t)b * HNUM + h) * 2048;
    const __half* kg = qg + (size_t)BWIN * HNUM * 2048;
    const __half* vg = kg + (size_t)BWIN * HNUM * 2048;
    const int tid = threadIdx.x;
#pragma unroll
    for (int s = 0; s < 2; s++) {
        int idx = tid + s * 128;
        int row = idx >> 2;
        int c8 = (idx & 3) * 8;
        *(uint4*)&Qs[row * 40 + c8] = __ldg((const uint4*)qg + idx);
        *(uint4*)&Ks[row * 40 + c8] = __ldg((const uint4*)kg + idx);
        *(uint4*)&Vs[row * 40 + c8] = __ldg((const uint4*)vg + idx);
    }
    __syncthreads();

    const int warp = tid >> 5;
    const int lane = tid & 31;
    const int g = lane >> 2;
    const int t = lane & 3;
    const int r0 = warp * 16;
    const unsigned aAddr = s2u(Qs) + ((r0 + (lane & 15)) * 40 + ((lane >> 4) & 1) * 8) * 2;
    const unsigned kAddr = s2u(Ks) +
        (((lane & 7) + ((lane >> 4) & 1) * 8) * 40 + ((lane >> 3) & 1) * 8) * 2;
    const unsigned vAddr = s2u(Vs) +
        (((lane & 7) + ((lane >> 3) & 1) * 8) * 40 + ((lane >> 4) & 1) * 8) * 2;

    float acc[8][4];
#pragma unroll
    for (int nt = 0; nt < 8; nt++)
#pragma unroll
        for (int j = 0; j < 4; j++) acc[nt][j] = 0.f;

#pragma unroll
    for (int kk = 0; kk < 2; kk++) {
        unsigned a[4];
        ldsm4(a, aAddr + kk * 16 * 2);
#pragma unroll
        for (int kn = 0; kn < 4; kn++) {
            unsigned bf[4];
            ldsm4(bf, kAddr + (kn * 16 * 40 + kk * 16) * 2);
            mma_f16(acc[kn * 2], a, bf[0], bf[1]);
            mma_f16(acc[kn * 2 + 1], a, bf[2], bf[3]);
        }
    }

    const float* rp = g_rpbm + ((size_t)w * HNUM + h) * 4096;
    const int rlo = r0 + g;
    const int rhi = rlo + 8;
    float mx0 = -1e30f;
    float mx1 = -1e30f;
#pragma unroll
    for (int nt = 0; nt < 8; nt++) {
        const int col = nt * 8 + 2 * t;
        float2 v0 = *(const float2*)(rp + rlo * 64 + col);
        float2 v1 = *(const float2*)(rp + rhi * 64 + col);
        acc[nt][0] += v0.x;
        acc[nt][1] += v0.y;
        acc[nt][2] += v1.x;
        acc[nt][3] += v1.y;
        mx0 = fmaxf(mx0, fmaxf(acc[nt][0], acc[nt][1]));
        mx1 = fmaxf(mx1, fmaxf(acc[nt][2], acc[nt][3]));
    }
    mx0 = fmaxf(mx0, __shfl_xor_sync(0xffffffffu, mx0, 1));
    mx0 = fmaxf(mx0, __shfl_xor_sync(0xffffffffu, mx0, 2));
    mx1 = fmaxf(mx1, __shfl_xor_sync(0xffffffffu, mx1, 1));
    mx1 = fmaxf(mx1, __shfl_xor_sync(0xffffffffu, mx1, 2));

    float s0 = 0.f;
    float s1 = 0.f;
#pragma unroll
    for (int nt = 0; nt < 8; nt++) {
        acc[nt][0] = exp2f((acc[nt][0] - mx0) * LOG2E);
        acc[nt][1] = exp2f((acc[nt][1] - mx0) * LOG2E);
        acc[nt][2] = exp2f((acc[nt][2] - mx1) * LOG2E);
        acc[nt][3] = exp2f((acc[nt][3] - mx1) * LOG2E);
        s0 += acc[nt][0] + acc[nt][1];
        s1 += acc[nt][2] + acc[nt][3];
    }
    s0 += __shfl_xor_sync(0xffffffffu, s0, 1);
    s0 += __shfl_xor_sync(0xffffffffu, s0, 2);
    s1 += __shfl_xor_sync(0xffffffffu, s1, 1);
    s1 += __shfl_xor_sync(0xffffffffu, s1, 2);

    float o[4][4];
#pragma unroll
    for (int nf = 0; nf < 4; nf++)
#pragma unroll
        for (int j = 0; j < 4; j++) o[nf][j] = 0.f;
#pragma unroll
    for (int kk = 0; kk < 4; kk++) {
        unsigned a[4];
        a[0] = pack2(acc[2 * kk][0], acc[2 * kk][1]);
        a[1] = pack2(acc[2 * kk][2], acc[2 * kk][3]);
        a[2] = pack2(acc[2 * kk + 1][0], acc[2 * kk + 1][1]);
        a[3] = pack2(acc[2 * kk + 1][2], acc[2 * kk + 1][3]);
#pragma unroll
        for (int d = 0; d < 2; d++) {
            unsigned bf[4];
            ldsm4t(bf, vAddr + (kk * 16 * 40 + d * 16) * 2);
            mma_f16(o[d * 2], a, bf[0], bf[1]);
            mma_f16(o[d * 2 + 1], a, bf[2], bf[3]);
        }
    }

    const float i0 = 1.f / s0;
    const float i1 = 1.f / s1;
    __half* yb = g_y16 + (size_t)b * 64 * 256 + h * 32;
    unsigned plo[4], phi[4];
#pragma unroll
    for (int nf = 0; nf < 4; nf++) {
        plo[nf] = pack2(o[nf][0] * i0, o[nf][1] * i0);
        phi[nf] = pack2(o[nf][2] * i1, o[nf][3] * i1);
    }
    trans4(plo, t);
    trans4(phi, t);
    *(uint4*)&yb[(size_t)rlo * 256 + t * 8] = make_uint4(plo[0], plo[1], plo[2], plo[3]);
    *(uint4*)&yb[(size_t)rhi * 256 + t * 8] = make_uint4(phi[0], phi[1], phi[2], phi[3]);
}

// ---------------------------------------------------------------------------
// Proj GEMM (legacy mma.sync, R7 version — fp32 stores already coalesced)
// ---------------------------------------------------------------------------
__global__ __launch_bounds__(256) void gemm_proj(const float* __restrict__ bias,
                                                 float* __restrict__ outp) {
    extern __shared__ __half smp[];
    __half* As = smp;
    __half* Bs = smp + 128 * ASTR;

    const int tid = threadIdx.x;
    const int warp = tid >> 5;
    const int lane = tid & 31;
    const int g = lane >> 2;
    const int t = lane & 3;
    const int wm = warp >> 2;
    const int wn = warp & 3;

    {
        const uint4* yg = (const uint4*)(g_y16 + (size_t)blockIdx.x * 128 * 256);
#pragma unroll
        for (int j = 0; j < 16; j++) {
            int idx = tid + j * 256;
            int row = idx >> 5;
            int c8 = (idx & 31) * 8;
            *(uint4*)&As[row * ASTR + c8] = __ldg(yg + idx);
        }
    }

    load_chunk(Bs, g_pw16, 0, 0, tid);

    float acc[4][4][4];
#pragma unroll
    for (int mt = 0; mt < 4; mt++)
#pragma unroll
        for (int nf = 0; nf < 4; nf++)
#pragma unroll
            for (int j = 0; j < 4; j++) acc[mt][nf][j] = 0.f;

    const unsigned aBase = s2u(As) + ((wm * 64 + (lane & 15)) * ASTR + ((lane >> 4) & 1) * 8) * 2;
    const unsigned bBase = s2u(Bs) +
        (((lane & 7) + ((lane >> 4) & 1) * 8) * BSTR + ((lane >> 3) & 1) * 8) * 2;

    int buf = 0;
    for (int it = 0; it < 8; it++) {
        asm volatile("cp.async.wait_group 0;");
        __syncthreads();
        if (it + 1 < 8) load_chunk(Bs, g_pw16, buf ^ 1, it + 1, tid);

        const int kc = it & 3;
#pragma unroll
        for (int ks = 0; ks < 4; ks++) {
            unsigned a[4][4];
#pragma unroll
            for (int mt = 0; mt < 4; mt++)
                ldsm4(a[mt], aBase + (mt * 16 * ASTR + kc * 64 + ks * 16) * 2);
#pragma unroll
            for (int nf2 = 0; nf2 < 2; nf2++) {
                unsigned b[4];
                ldsm4(b, bBase + (buf * 128 * BSTR + (wn * 32 + nf2 * 16) * BSTR + ks * 16) * 2);
#pragma unroll
                for (int mt = 0; mt < 4; mt++) {
                    mma_f16(acc[mt][nf2 * 2], a[mt], b[0], b[1]);
                    mma_f16(acc[mt][nf2 * 2 + 1], a[mt], b[2], b[3]);
                }
            }
        }

        if (kc == 3) {
            const int nt = it >> 2;
            const int colb = nt * 128 + wn * 32;
#pragma unroll
            for (int mt = 0; mt < 4; mt++) {
#pragma unroll
                for (int hf = 0; hf < 2; hf++) {
                    const int row = (int)(blockIdx.x * 128) + wm * 64 + mt * 16 + g + hf * 8;
#pragma unroll
                    for (int nf = 0; nf < 4; nf++) {
                        const int col = colb + nf * 8 + 2 * t;
                        float2 o;
                        o.x = acc[mt][nf][hf * 2] + __ldg(bias + col);
                        o.y = acc[mt][nf][hf * 2 + 1] + __ldg(bias + col + 1);
                        *(float2*)&outp[(size_t)row * 256 + col] = o;
                    }
                }
            }
#pragma unroll
            for (int mt = 0; mt < 4; mt++)
#pragma unroll
                for (int nf = 0; nf < 4; nf++)
#pragma unroll
                    for (int j = 0; j < 4; j++) acc[mt][nf][j] = 0.f;
        }
        buf ^= 1;
    }
}

// ---------------------------------------------------------------------------
// launch
// ---------------------------------------------------------------------------
extern "C" void kernel_launch(void* const* d_in, const int* in_sizes, int n_in,
                              void* d_out, int out_size) {
    const float* x           = (const float*)d_in[0];
    const float* mask        = (const float*)d_in[1];
    const float* qkv_w       = (const float*)d_in[2];
    const float* q_bias      = (const float*)d_in[3];
    const float* v_bias      = (const float*)d_in[4];
    const float* logit_scale = (const float*)d_in[5];
    const float* cpb_w1      = (const float*)d_in[6];
    const float* cpb_b1      = (const float*)d_in[7];
    const float* cpb_w2      = (const float*)d_in[8];
    const float* proj_w      = (const float*)d_in[9];
    const float* proj_b      = (const float*)d_in[10];
    const float* rel_table   = (const float*)d_in[11];
    const int*   rel_index   = (const int*)d_in[12];
    float* out = (float*)d_out;

    cudaFuncSetAttribute(gemm_qkv, cudaFuncAttributeMaxDynamicSharedMemorySize, SMEM_GEMM);
    cudaFuncSetAttribute(gemm_proj, cudaFuncAttributeMaxDynamicSharedMemorySize, SMEM_GEMM);

    wcvt_kernel<<<1024, 256>>>(qkv_w, proj_w);
    cpb_table_kernel<<<127, 256>>>(rel_table, cpb_w1, cpb_b1, cpb_w2);
    rpbm_kernel<<<dim3(64, 8), 256>>>(rel_index, mask);
    gemm_qkv<<<2048, 256, SMEM_GEMM>>>(x, q_bias, v_bias, logit_scale);
    attn16<<<BWIN * HNUM, 128>>>();
    gemm_proj<<<2048, 256, SMEM_GEMM>>>(proj_b, out);
}